// round 11
// baseline (speedup 1.0000x reference)
#include <cuda_runtime.h>
#include <cuda_bf16.h>
#include <math.h>

// Fixed problem shapes
#define B_DIM 64
#define H_DIM 512
#define W_DIM 1024
#define P 8
#define HP (H_DIM / P)            // 64
#define WP (W_DIM / P)            // 128
#define N_LOSS (B_DIM * HP * WP)  // 524288
#define NBLK 512                  // 64 patches * 8 slices; BCE coverage:
                                  // 512 blk * 256 thr * 4 elem = 524288 exactly

__device__ __align__(16) int    g_count_parts[NBLK];  // per-slice counts
__device__ __align__(16) double g_partials[NBLK];     // per-block log sums
__device__ double g_corr[P * P];  // per-patch correction sums (blocks 0..63)
__device__ int    g_ticket = 0;   // finale election; reset each run

__device__ __forceinline__ double warp_sum_d(double v) {
#pragma unroll
    for (int o = 16; o > 0; o >>= 1) v += __shfl_down_sync(0xffffffffu, v, o);
    return v;
}

__global__ void __launch_bounds__(256)
k_fused(const int* __restrict__ targets, const float* __restrict__ pc,
        float* __restrict__ out) {
    const int tid  = threadIdx.x;
    const int blk  = blockIdx.x;
    const int lane = tid & 31, warp = tid >> 5;   // 8 warps

    // ---- issue ALL loads up front: 1 float4 (pc) + 8 int4 (targets) ----
    const float4 v = ((const float4*)pc)[blk * 256 + tid];

    // patch (pi,pj) = (blk>>3 >>3, blk>>3 &7), slice = blk&7.
    // Key simplification: r = slice*8+rr  =>  r>>3 == slice (const),
    // r&7 == rr. So batch index a = pi*8+slice is LOOP-INVARIANT and the 8
    // rows are consecutive H-rows b = pj*8+rr: one base pointer + rr*W_DIM
    // immediate offsets -> 8 front-batched LDG.128 off a single register.
    const int patch = blk >> 3, slice = blk & 7;
    const int pi = patch >> 3, pj = patch & 7;
    const int a = pi * P + slice;                 // batch idx (<64), invariant
    const int4* base = (const int4*)(targets + (size_t)a * H_DIM * W_DIM
                                             + (size_t)(pj * P) * W_DIM) + tid;
    int cacc = 0;
#pragma unroll
    for (int rr = 0; rr < 8; rr++) {
        const int4 t4 = base[rr * (W_DIM / 4)];   // +rr*4096B immediate
        cacc += (t4.x == 2) + (t4.y == 2) + (t4.z == 2) + (t4.w == 2);
    }

    // ---- parallel corner-correction precompute: blocks 0..63 = patch id ----
    // Correction per corner elem (b, i, j): log(p/(1-p)); gating applied in
    // finale. Block blk<64 handles patch (i=blk>>3, j=blk&7), thread tid<64
    // handles batch b=tid. pc idx = b*8192 + i*128 + j.
    double corr = 0.0;
    if (blk < P * P && tid < B_DIM) {
        const int ci = blk >> 3, cj = blk & 7;
        const float pv = pc[tid * (HP * WP) + ci * WP + cj];
        corr = (double)__logf(__fdividef(pv, 1.0f - pv));
    }

    // ---- BCE: log of PRODUCT of (1-p) over this thread's 4 elems ----
    // (1-p) in [1e-4, 1) -> product in [1e-16, 1): no under/overflow.
    const float prod = (1.0f - v.x) * (1.0f - v.y)
                     * (1.0f - v.z) * (1.0f - v.w);
    double acc = (double)__logf(prod);

    // ---- fused block reductions (int via REDUX, double via shfl) ----
    __shared__ int    shi[8];
    __shared__ double shw[8];
    __shared__ double shc[2];
    cacc = __reduce_add_sync(0xffffffffu, cacc);
    acc  = warp_sum_d(acc);
    if (warp < 2) {                               // corr lives in warps 0,1
        const double cw = warp_sum_d(corr);
        if (lane == 0) shc[warp] = cw;
    }
    if (lane == 0) { shi[warp] = cacc; shw[warp] = acc; }
    __syncthreads();
    if (warp == 0) {
        int ci2 = (lane < 8) ? shi[lane] : 0;
        ci2 = __reduce_add_sync(0xffffffffu, ci2);
        double dv = (lane < 8) ? shw[lane] : 0.0;
        dv = warp_sum_d(dv);
        if (lane == 0) {
            g_count_parts[blk] = ci2;
            g_partials[blk]    = dv;
            if (blk < P * P) g_corr[blk] = shc[0] + shc[1];
        }
    }

    // ----- last-block finale election -----
    __threadfence();                              // publish our partials
    __shared__ int s_last;
    if (tid == 0) {
        const int t = atomicAdd(&g_ticket, 1);
        s_last = (t == NBLK - 1);
    }
    __syncthreads();
    if (!s_last) return;
    __threadfence();                              // acquire others' writes

    // (1) BCE partials: 512 doubles as 256 double2 (one LDG.128 per thread)
    const double2 p2 = ((const double2*)g_partials)[tid];
    double facc = p2.x + p2.y;

    // (2) gated corrections: tid<64 reduces its patch's 8 count slices
    //     (two int4 loads) and, if 0 < count < 64, adds the precomputed sum.
    if (tid < P * P) {
        const int4 c0 = ((const int4*)g_count_parts)[tid * 2];
        const int4 c1 = ((const int4*)g_count_parts)[tid * 2 + 1];
        const int c = c0.x + c0.y + c0.z + c0.w + c1.x + c1.y + c1.z + c1.w;
        if (c > 0 && c < P * P) facc += g_corr[tid];
    }

    // (3) warp-shuffle tree reduce + output
    __shared__ double shf[8];
    facc = warp_sum_d(facc);
    if (lane == 0) shf[warp] = facc;
    __syncthreads();
    if (warp == 0) {
        double fv = (lane < 8) ? shf[lane] : 0.0;
        fv = warp_sum_d(fv);
        if (lane == 0) {
            out[0] = (float)(-fv / (double)N_LOSS);
            g_ticket = 0;                         // reset for next graph replay
        }
    }
}

extern "C" void kernel_launch(void* const* d_in, const int* in_sizes, int n_in,
                              void* d_out, int out_size) {
    // Resolve inputs by element count (pc = 524288 f32, targets = 33554432 i32)
    // so we don't depend on metadata ordering.
    const float* pc;
    const int*   targets;
    if (in_sizes[0] == N_LOSS) {
        pc      = (const float*)d_in[0];
        targets = (const int*)d_in[1];
    } else {
        targets = (const int*)d_in[0];
        pc      = (const float*)d_in[1];
    }
    float* out = (float*)d_out;

    k_fused<<<NBLK, 256>>>(targets, pc, out);
}